// round 6
// baseline (speedup 1.0000x reference)
#include <cuda_runtime.h>
#include <cstdint>
#include <math.h>

#define NT 16384
#define HH 2048
#define NE 64
#define NB 4
#define NS 4096
#define TM 128          // tokens per CTA
#define KC 32           // K elems per tile
#define NK2 (KC/2)      // 16 k-pairs per tile
#define NTILES (HH/KC)  // 64
#define THREADS 256
#define SMEM_BYTES 49664

// persistent scratch (allocation-free rule: __device__ globals)
__device__ float g_ssum[NB * NE];
__device__ int   g_cnt[NB * NE];

// ---------------- helpers ----------------
__device__ __forceinline__ uint32_t smem_u32(const void* p) {
    uint32_t a;
    asm("{ .reg .u64 t; cvta.to.shared.u64 t, %1; cvt.u32.u64 %0, t; }" : "=r"(a) : "l"(p));
    return a;
}
#define FMA2(acc, a2, b2) \
    asm("fma.rn.f32x2 %0, %1, %2, %0;" : "+l"(acc) : "l"(a2), "l"(b2))

// ---------------- main gate kernel ----------------
__global__ __launch_bounds__(THREADS, 1)
void k_gate(const float* __restrict__ X, const float* __restrict__ W,
            float* __restrict__ out, int wbase) {
    extern __shared__ char smem[];
    const int tid  = threadIdx.x;
    const int wid  = tid >> 5;          // expert group: experts wid*8 .. wid*8+7
    const int lane = tid & 31;          // tokens lane*4 .. lane*4+3
    const uint32_t sb = smem_u32(smem);
    const int tokBase = blockIdx.x * TM;

    int* scnt = (int*)(smem + 49152);
    if (tid < NE) scnt[tid] = 0;

    // smem layout (k-pair major):
    //   xs[s][k2][tok][2]  : sb + s*16384 + k2*1024 + tok*8
    //   ws[s][k2][exp][2]  : sb + 32768 + s*8192 + k2*512 + exp*8
    const uint32_t XS0 = sb;
    const uint32_t WS0 = sb + 32768u;

    // ---- gmem mapping ----
    // X: xtok = tid&127 (warp = 32 consecutive tokens), xqsel = tid>>7
    //    thread covers quads (xqsel*4 + p), p = 0..3  (64B contiguous)
    const int xtok  = tid & 127;
    const int xqsel = tid >> 7;
    const float* xp = X + (size_t)(tokBase + xtok) * HH + xqsel * 16;
    // W: we = tid&63, wq2 = tid>>6 (0..3); quads wq2 + 4p, p = 0..1
    const int we  = tid & 63;
    const int wq2 = tid >> 6;
    const float* wp = W + (size_t)we * HH + wq2 * 4;

    // accumulators: acc2[i][e] = {sum_even_k, sum_odd_k} for (token lane*4+i, expert wid*8+e)
    unsigned long long acc2[4][8];
#pragma unroll
    for (int i = 0; i < 4; i++)
#pragma unroll
        for (int e = 0; e < 8; e++) acc2[i][e] = 0ull;

    // ---- prologue: load tile 0 into regs ----
    float4 xv[4];
    float4 wv[2];
#pragma unroll
    for (int p = 0; p < 4; p++) xv[p] = *(const float4*)(xp + p * 4);
#pragma unroll
    for (int p = 0; p < 2; p++) wv[p] = *(const float4*)(wp + p * 16);

    const uint32_t aOff = (uint32_t)lane * 32u;   // lane*4 tokens * 8B
    const uint32_t bOff = (uint32_t)wid * 64u;    // wid*8 experts * 8B

    for (int t = 0; t < NTILES; t++) {
        const int s = t & 1;
        const uint32_t xsb = XS0 + (uint32_t)s * 16384u;
        const uint32_t wsb = WS0 + (uint32_t)s * 8192u;

        // ---- STS tile t (k-pair major; no transpose conflicts) ----
#pragma unroll
        for (int p = 0; p < 4; p++) {
            const uint32_t k2 = (uint32_t)((xqsel * 4 + p) * 2);
            const uint32_t a0 = xsb + k2 * 1024u + (uint32_t)xtok * 8u;
            asm volatile("st.shared.v2.f32 [%0], {%1,%2};" :: "r"(a0),          "f"(xv[p].x), "f"(xv[p].y));
            asm volatile("st.shared.v2.f32 [%0], {%1,%2};" :: "r"(a0 + 1024u),  "f"(xv[p].z), "f"(xv[p].w));
        }
#pragma unroll
        for (int p = 0; p < 2; p++) {
            const uint32_t k2 = (uint32_t)((wq2 + 4 * p) * 2);
            const uint32_t a0 = wsb + k2 * 512u + (uint32_t)we * 8u;
            asm volatile("st.shared.v2.f32 [%0], {%1,%2};" :: "r"(a0),         "f"(wv[p].x), "f"(wv[p].y));
            asm volatile("st.shared.v2.f32 [%0], {%1,%2};" :: "r"(a0 + 512u),  "f"(wv[p].z), "f"(wv[p].w));
        }

        // ---- prefetch tile t+1 into regs (in flight during FMA) ----
        if (t + 1 < NTILES) {
            const int k0 = (t + 1) * KC;
#pragma unroll
            for (int p = 0; p < 4; p++) xv[p] = *(const float4*)(xp + k0 + p * 4);
#pragma unroll
            for (int p = 0; p < 2; p++) wv[p] = *(const float4*)(wp + k0 + p * 16);
        }

        __syncthreads();   // single barrier per tile (double-buffered)

        // ---- FMA phase over buf s ----
        const uint32_t aB = xsb + aOff;
        const uint32_t bB = wsb + bOff;
#pragma unroll
        for (int k2 = 0; k2 < NK2; k2++) {
            unsigned long long ap[4], bp[8];
            asm("ld.shared.v2.u64 {%0,%1}, [%2];"
                : "=l"(ap[0]), "=l"(ap[1]) : "r"(aB + (uint32_t)k2 * 1024u));
            asm("ld.shared.v2.u64 {%0,%1}, [%2];"
                : "=l"(ap[2]), "=l"(ap[3]) : "r"(aB + (uint32_t)k2 * 1024u + 16u));
            asm("ld.shared.v2.u64 {%0,%1}, [%2];"
                : "=l"(bp[0]), "=l"(bp[1]) : "r"(bB + (uint32_t)k2 * 512u));
            asm("ld.shared.v2.u64 {%0,%1}, [%2];"
                : "=l"(bp[2]), "=l"(bp[3]) : "r"(bB + (uint32_t)k2 * 512u + 16u));
            asm("ld.shared.v2.u64 {%0,%1}, [%2];"
                : "=l"(bp[4]), "=l"(bp[5]) : "r"(bB + (uint32_t)k2 * 512u + 32u));
            asm("ld.shared.v2.u64 {%0,%1}, [%2];"
                : "=l"(bp[6]), "=l"(bp[7]) : "r"(bB + (uint32_t)k2 * 512u + 48u));
#pragma unroll
            for (int i = 0; i < 4; i++)
#pragma unroll
                for (int e = 0; e < 8; e++)
                    FMA2(acc2[i][e], ap[i], bp[e]);
        }
    }

    __syncthreads();   // buffers free; reuse as logits

    // ---- accumulators -> logits smem [128][66] (logit = lo + hi) ----
    float* Lg = (float*)smem;
#pragma unroll
    for (int i = 0; i < 4; i++) {
        const int tok = lane * 4 + i;
#pragma unroll
        for (int e = 0; e < 8; e += 2) {
            uint32_t lo0, hi0, lo1, hi1;
            asm("mov.b64 {%0,%1}, %2;" : "=r"(lo0), "=r"(hi0) : "l"(acc2[i][e]));
            asm("mov.b64 {%0,%1}, %2;" : "=r"(lo1), "=r"(hi1) : "l"(acc2[i][e + 1]));
            float s0 = __uint_as_float(lo0) + __uint_as_float(hi0);
            float s1 = __uint_as_float(lo1) + __uint_as_float(hi1);
            asm volatile("st.shared.v2.f32 [%0], {%1,%2};"
                         :: "r"(sb + (uint32_t)(tok * 66 + wid * 8 + e) * 4u), "f"(s0), "f"(s1));
        }
    }
    __syncthreads();

    // ---- per-token softmax / top-2 ----
    if (tid < TM) {
        float v[64];
#pragma unroll
        for (int e = 0; e < NE; e++) v[e] = Lg[tid * 66 + e];

        float m = -1e30f;
#pragma unroll
        for (int e = 0; e < NE; e++) m = fmaxf(m, v[e]);

        float Z = 0.0f, b1 = -1e30f, b2 = -1e30f;
        int i1 = 0, i2 = 0;
#pragma unroll
        for (int e = 0; e < NE; e++) {
            float x = v[e];
            float ex = __expf(x - m);
            v[e] = ex;
            Z += ex;
            if (x > b1)      { b2 = b1; i2 = i1; b1 = x; i1 = e; }
            else if (x > b2) { b2 = x;  i2 = e; }
        }
        float invZ = 1.0f / Z;
        float s1 = v[i1] * invZ;
        float s2 = v[i2] * invZ;
        float den = s1 + s2 + 1e-20f;

        int gt = tokBase + tid;
        out[gt * 2 + 0] = (float)i1;
        out[gt * 2 + 1] = (float)i2;
        out[wbase + gt * 2 + 0] = s1 / den;
        out[wbase + gt * 2 + 1] = s2 / den;

        atomicAdd(&scnt[i1], 1);
        atomicAdd(&scnt[i2], 1);

#pragma unroll
        for (int e = 0; e < NE; e++) Lg[tid * 66 + e] = v[e] * invZ;
    }
    __syncthreads();

    if (tid < NE) {
        float ssum = 0.0f;
        for (int r = 0; r < TM; r++) ssum += Lg[r * 66 + tid];
        const int b = tokBase >> 12;
        atomicAdd(&g_ssum[b * NE + tid], ssum);
        int c = scnt[tid];
        if (c) atomicAdd(&g_cnt[b * NE + tid], c);
    }
}

// ---------------- aux loss + scratch reset ----------------
__global__ void k_aux(float* __restrict__ out, int aux_idx) {
    __shared__ float red[NB * NE];
    int i = threadIdx.x;
    float v = (float)g_cnt[i] * ((float)NE / (float)(NS * 2)) * (g_ssum[i] / (float)NS);
    red[i] = v;
    g_cnt[i] = 0;       // reset for next graph replay
    g_ssum[i] = 0.0f;
    __syncthreads();
    for (int s = 128; s > 0; s >>= 1) {
        if (i < s) red[i] += red[i + s];
        __syncthreads();
    }
    if (i == 0) out[aux_idx] = red[0] / (float)NB * 0.1f;
}

extern "C" void kernel_launch(void* const* d_in, const int* in_sizes, int n_in,
                              void* d_out, int out_size) {
    const float* X = (const float*)d_in[0];   // [4,4096,2048] fp32
    const float* W = (const float*)d_in[1];   // [64,2048] fp32
    float* out = (float*)d_out;
    const int wbase = (out_size - 1) / 2;     // 32768

    cudaFuncSetAttribute(k_gate, cudaFuncAttributeMaxDynamicSharedMemorySize, SMEM_BYTES);

    k_gate<<<NT / TM, THREADS, SMEM_BYTES>>>(X, W, out, wbase);
    k_aux<<<1, NB * NE>>>(out, out_size - 1);
}